// round 3
// baseline (speedup 1.0000x reference)
#include <cuda_runtime.h>
#include <cuda_bf16.h>

// Rows = 4194304, features = 16 fp32 per row, output = rows x 3 fp32 one-hot.
// selected = (f11 > 0.5) ? 0 : ((f4+f5 > f6+f7) ? 1 : 2)
//
// Pure HBM-bound stream: both 32B sectors of each 64B row are needed
// (cols 4-7 -> sector 0, col 11 -> sector 1), so DRAM read = 256 MiB fixed,
// write = 48 MiB. Strategy: deep per-warp MLP (16 front-batched loads) +
// streaming cache hints (single-touch data).

#define ROWS_PER_THREAD 8

__global__ __launch_bounds__(256)
void gating_kernel(const float4* __restrict__ in,   // 4 float4 per row
                   float4* __restrict__ out,        // 6 float4 per thread
                   int n_rows)
{
    int t = blockIdx.x * blockDim.x + threadIdx.x;
    int row0 = t * ROWS_PER_THREAD;
    if (row0 >= n_rows) return;

    const float* inf = (const float*)in;

    // Front-batch all loads for maximum memory-level parallelism.
    float4 c47[ROWS_PER_THREAD];
    float  c11[ROWS_PER_THREAD];
#pragma unroll
    for (int i = 0; i < ROWS_PER_THREAD; i++) {
        int r = row0 + i;
        c47[i] = __ldcs(&in[r * 4 + 1]);          // cols 4..7, LDG.128.CS
        c11[i] = __ldcs(&inf[r * 16 + 11]);       // col 11,    LDG.32.CS
    }

    float o[ROWS_PER_THREAD * 3];
#pragma unroll
    for (int i = 0; i < ROWS_PER_THREAD; i++) {
        float cyc = c47[i].x + c47[i].y;   // f4 + f5
        float hf  = c47[i].z + c47[i].w;   // f6 + f7
        bool e0 = c11[i] > 0.5f;
        bool e1 = !e0 && (cyc > hf);
        bool e2 = !e0 && !e1;
        o[i * 3 + 0] = e0 ? 1.0f : 0.0f;
        o[i * 3 + 1] = e1 ? 1.0f : 0.0f;
        o[i * 3 + 2] = e2 ? 1.0f : 0.0f;
    }

    // 8 rows * 3 floats = 24 floats = 6 float4, base = t*96 bytes (16B aligned)
    float4* dst = out + t * 6;
#pragma unroll
    for (int j = 0; j < 6; j++) {
        __stcs(&dst[j], make_float4(o[j*4+0], o[j*4+1], o[j*4+2], o[j*4+3]));
    }
}

extern "C" void kernel_launch(void* const* d_in, const int* in_sizes, int n_in,
                              void* d_out, int out_size)
{
    const float* features = (const float*)d_in[0];
    float* out = (float*)d_out;
    int n_rows = in_sizes[0] / 16;                 // 4194304

    int n_threads = n_rows / ROWS_PER_THREAD;      // 524288 (exact)
    int block = 256;
    int grid = n_threads / block;                  // 2048 (exact)
    gating_kernel<<<grid, block>>>((const float4*)features, (float4*)out, n_rows);
}

// round 4
// speedup vs baseline: 1.0569x; 1.0569x over previous
#include <cuda_runtime.h>
#include <cuda_bf16.h>

// Rows = 4194304, features = 16 fp32 per row, output = rows x 3 fp32 one-hot.
// selected = (f11 > 0.5) ? 0 : ((f4+f5 > f6+f7) ? 1 : 2)
//
// HBM-bound stream. Both 32B sectors of each 64B row are needed
// (cols 4-7 -> sector 0, col 11 -> sector 1): DRAM read = 256 MiB fixed,
// write = 48 MiB. R3 showed latency hiding here is occupancy-driven:
// keep RPT=4 (28 regs, occ ~81%). Only change vs R2: evict-first stores
// (__stcs) so write-once output doesn't pollute L2 against the read stream.

#define ROWS_PER_THREAD 4

__global__ __launch_bounds__(256)
void gating_kernel(const float4* __restrict__ in,   // 4 float4 per row
                   float4* __restrict__ out,        // 3 float4 per thread
                   int n_rows)
{
    int t = blockIdx.x * blockDim.x + threadIdx.x;
    int row0 = t * ROWS_PER_THREAD;
    if (row0 >= n_rows) return;

    // Front-batch loads (8 per thread) for MLP; default cache policy.
    float4 c47[ROWS_PER_THREAD];
    float  c11[ROWS_PER_THREAD];
#pragma unroll
    for (int i = 0; i < ROWS_PER_THREAD; i++) {
        int r = row0 + i;
        c47[i] = in[r * 4 + 1];            // cols 4..7  (LDG.128)
        c11[i] = in[r * 4 + 2].w;          // col 11     (LDG.32)
    }

    float o[ROWS_PER_THREAD * 3];
#pragma unroll
    for (int i = 0; i < ROWS_PER_THREAD; i++) {
        float cyc = c47[i].x + c47[i].y;   // f4 + f5
        float hf  = c47[i].z + c47[i].w;   // f6 + f7
        bool e0 = c11[i] > 0.5f;
        bool e1 = !e0 && (cyc > hf);
        bool e2 = !e0 && !e1;
        o[i * 3 + 0] = e0 ? 1.0f : 0.0f;
        o[i * 3 + 1] = e1 ? 1.0f : 0.0f;
        o[i * 3 + 2] = e2 ? 1.0f : 0.0f;
    }

    // 4 rows * 3 floats = 12 floats = 3 float4, base = t*48 bytes (16B aligned)
    float4* dst = out + t * 3;
    __stcs(&dst[0], make_float4(o[0], o[1], o[2],  o[3]));
    __stcs(&dst[1], make_float4(o[4], o[5], o[6],  o[7]));
    __stcs(&dst[2], make_float4(o[8], o[9], o[10], o[11]));
}

extern "C" void kernel_launch(void* const* d_in, const int* in_sizes, int n_in,
                              void* d_out, int out_size)
{
    const float* features = (const float*)d_in[0];
    float* out = (float*)d_out;
    int n_rows = in_sizes[0] / 16;                 // 4194304

    int n_threads = n_rows / ROWS_PER_THREAD;      // 1048576 (exact)
    int block = 256;
    int grid = n_threads / block;                  // 4096 (exact)
    gating_kernel<<<grid, block>>>((const float4*)features, (float4*)out, n_rows);
}